// round 10
// baseline (speedup 1.0000x reference)
#include <cuda_runtime.h>

// Problem constants
#define TSEQ 1024
#define NB   32      // batch
#define ID   512     // input dim
#define HD   512     // hidden dim
#define GD   2048    // 4*H gate rows
#define NBLK 128     // merged blocks: each does 4 units, BOTH directions
#define REC_THREADS 256

typedef unsigned long long ull;

// Scratch (device globals: no runtime allocation allowed)
__device__ float g_xw[(size_t)TSEQ * GD * NB];   // [t][g][b], 256MB
__device__ float g_hbuf[2][2][HD * NB];          // [dir][ping][u*32 + b]
__device__ unsigned g_cnt[2][8];   // tree barrier: 8 groups of 16 (monotonic)
__device__ unsigned g_root[2];     // tree root counters (monotonic)
__device__ unsigned g_gen[2];      // generation flags (monotonic)

// ---------------------------------------------------------------------------
// packed fp32x2 ops (Blackwell)
// ---------------------------------------------------------------------------
__device__ __forceinline__ void ffma2(ull& d, ull a, ull b) {
    asm("fma.rn.f32x2 %0, %1, %2, %0;" : "+l"(d) : "l"(a), "l"(b));
}
__device__ __forceinline__ ull addf2(ull a, ull b) {
    ull r;
    asm("add.rn.f32x2 %0, %1, %2;" : "=l"(r) : "l"(a), "l"(b));
    return r;
}
__device__ __forceinline__ ull dup2(float x) {
    ull r;
    asm("mov.b64 %0, {%1, %1};" : "=l"(r) : "f"(x));
    return r;
}
__device__ __forceinline__ float pairsum(ull v) {
    float2 f = *reinterpret_cast<float2*>(&v);
    return f.x + f.y;
}

__device__ __forceinline__ unsigned atom_add_acqrel(unsigned* p, unsigned v) {
    unsigned old;
    asm volatile("atom.acq_rel.gpu.add.u32 %0, [%1], %2;"
                 : "=r"(old) : "l"(p), "r"(v) : "memory");
    return old;
}
__device__ __forceinline__ unsigned ld_acquire(const unsigned* p) {
    unsigned v;
    asm volatile("ld.acquire.gpu.u32 %0, [%1];" : "=r"(v) : "l"(p) : "memory");
    return v;
}
__device__ __forceinline__ void st_release(unsigned* p, unsigned v) {
    asm volatile("st.release.gpu.u32 [%0], %1;" :: "l"(p), "r"(v) : "memory");
}

__device__ __forceinline__ float sigf(float x) {
    return __fdividef(1.f, 1.f + __expf(-x));
}
__device__ __forceinline__ float tanhfast(float x) {
    return __fdividef(2.f, 1.f + __expf(-2.f * x)) - 1.f;
}

// Tree barrier: arrive completing generation G -> release G+1. 128 blocks,
// 8 groups x 16. Counters monotonic (graph-replay safe).
__device__ __forceinline__ void bar_arrive(int d, unsigned G, int grp) {
    unsigned old = atom_add_acqrel(&g_cnt[d][grp], 1u);
    if (old == G * 16u + 15u) {
        unsigned r = atom_add_acqrel(&g_root[d], 1u);
        if (r == G * 8u + 7u) st_release(&g_gen[d], G + 1u);
    }
}
__device__ __forceinline__ void bar_wait(int d, unsigned G) {
    while ((int)(ld_acquire(&g_gen[d]) - (G + 1u)) < 0) { }
}

// ---------------------------------------------------------------------------
// xw[t][g][b] = sum_i x[t][b][i] * W_ih[g][i] + (b_ih[g] + b_hh[g])
// Also zeroes its 2KB slice of d_out.
// ---------------------------------------------------------------------------
__global__ __launch_bounds__(256) void xw_gemm(
    const float* __restrict__ x,
    const float* __restrict__ Wih,
    const float* __restrict__ bih,
    const float* __restrict__ bhh,
    float4* __restrict__ out4)
{
    __shared__ float xs[NB * 36];
    __shared__ float ws[64 * 32];

    if (threadIdx.x < 128)
        out4[(size_t)blockIdx.x * 128 + threadIdx.x] = make_float4(0.f, 0.f, 0.f, 0.f);

    int t   = blockIdx.x >> 5;
    int g0  = (blockIdx.x & 31) << 6;
    int tid = threadIdx.x;
    int gg  = tid >> 5;
    int b   = tid & 31;

    ull acc[8];
#pragma unroll
    for (int j = 0; j < 8; j++) acc[j] = 0ull;

    const float* xt = x + (size_t)t * NB * ID;

    for (int k0 = 0; k0 < ID; k0 += 32) {
#pragma unroll
        for (int r = 0; r < 4; r++) {
            int bl = (tid >> 5) + (r << 3);
            int kk = tid & 31;
            xs[bl * 36 + kk] = xt[bl * ID + k0 + kk];
        }
#pragma unroll
        for (int r = 0; r < 8; r++) {
            int gl = (tid >> 5) + (r << 3);
            int kk = tid & 31;
            ws[gl * 32 + kk] = Wih[(size_t)(g0 + gl) * ID + k0 + kk];
        }
        __syncthreads();

#pragma unroll
        for (int kk = 0; kk < 32; kk += 4) {
            ulonglong2 xv = *(const ulonglong2*)&xs[b * 36 + kk];
#pragma unroll
            for (int j = 0; j < 8; j++) {
                ulonglong2 wv = *(const ulonglong2*)&ws[(gg * 8 + j) * 32 + kk];
                ffma2(acc[j], xv.x, wv.x);
                ffma2(acc[j], xv.y, wv.y);
            }
        }
        __syncthreads();
    }

    float* outp = g_xw + (size_t)t * GD * NB;
#pragma unroll
    for (int j = 0; j < 8; j++) {
        int g = g0 + gg * 8 + j;
        outp[g * NB + b] = pairsum(acc[j]) + bih[g] + bhh[g];
    }
}

// ---------------------------------------------------------------------------
// Merged-direction persistent zoneout-LSTM recurrence.
// 128 blocks x 256 threads. Block owns hidden units j0..j0+3 for BOTH
// directions (same W_hh rows -> one 32KB W tile). Per step: fwd phase then
// bwd phase; cell math of one direction overlaps GEMV of the other, hiding
// barrier + L2 latency. c and h_old live in registers (same thread owns the
// (unit,batch) cell across all steps).
// GEMV per direction: 16 gate rows x 32 b x 512 k over 8 warps (64k each);
// lane = (ks = lane>>3 [4-way k], rg = (lane>>2)&1 [8 rows], bg = lane&3
// [8 batches]); acc[8][4] ull; fold = R9's verified 2-round shfl_xor.
// ---------------------------------------------------------------------------
__global__ __launch_bounds__(REC_THREADS, 1) void lstm_rec(
    const float* __restrict__ Whh, float* __restrict__ out)
{
    extern __shared__ float smem[];
    float* Wt  = smem;                   // 8320:  [reg=k>>4][kk*16 + row], stride 260
    float* Hs  = smem + 8320;            // 16448: [reg=k>>4][kk*32 + b],   stride 514
    float* gbf = smem + 8320 + 16448;    // 4352:  fwd partials [w][row*34 + b]
    float* gbb = gbf + 4352;             // 4352:  bwd partials

    int bid  = blockIdx.x;
    int j0   = bid << 2;          // 4 hidden units
    int grp  = bid & 7;
    int tid  = threadIdx.x;
    int w    = tid >> 5;
    int lane = tid & 31;
    int ks   = lane >> 3;
    int rg   = (lane >> 2) & 1;
    int bg   = lane & 3;
    int half = w >> 2;            // 0 = fwd cell group, 1 = bwd cell group
    int wc   = w & 3;             // unit within block for cell phase
    int gu   = j0 + wc;

    // Stage W_hh: 16 local rows (r: gate=r>>2, unit=r&3 -> global (r>>2)*512+j0+(r&3))
#pragma unroll 4
    for (int i = 0; i < 32; i++) {
        int e = tid + (i << 8);
        int r = e >> 9;
        int k = e & 511;
        int grow = ((r >> 2) << 9) + j0 + (r & 3);
        Wt[(k >> 4) * 260 + (k & 15) * 16 + r] = Whh[(size_t)grow * HD + k];
    }

    // init: this thread owns cell (gu, lane) of direction `half`
    float c_reg = 0.f;
    float h_reg = 0.f;
    g_hbuf[half][0][gu * 32 + lane] = 0.f;

    unsigned genf = ld_acquire(&g_gen[0]);
    unsigned genb = ld_acquire(&g_gen[1]);
    __syncthreads();
    if (tid == 0) { bar_arrive(0, genf, grp); bar_arrive(1, genb, grp); }

    const float4* Wr = (const float4*)Wt + ((w << 2) | ks) * 65;   // 260/4
    const float*  Hr = Hs + ((w << 2) | ks) * 514;

    for (int s = 0; s < TSEQ; s++) {
#pragma unroll
        for (int d = 0; d < 2; d++) {
            // ---- phase d: wait gen, copy h, GEMV, publish, cell+arrive ----
            unsigned G = d ? genb : genf;
            bar_wait(d, G);
            if (d) genb++; else genf++;

            int t = d ? (TSEQ - 1 - s) : s;
            const float* xw_t = g_xw + (size_t)t * GD * NB;

            // cell-group prefetch of xw (hidden under GEMV)
            float xg0 = 0.f, xg1 = 0.f, xg2 = 0.f, xg3 = 0.f;
            if (half == d) {
                xg0 = xw_t[(0 * HD + gu) * NB + lane];
                xg1 = xw_t[(1 * HD + gu) * NB + lane];
                xg2 = xw_t[(2 * HD + gu) * NB + lane];
                xg3 = xw_t[(3 * HD + gu) * NB + lane];
            }

            // per-warp copy of its own h k-slice [64w, 64w+64) into region layout
            {
                const float4* hsrc = (const float4*)g_hbuf[d][s & 1];
#pragma unroll
                for (int i = 0; i < 16; i++) {
                    int e  = (i << 5) + lane;   // 0..511
                    int kl = e >> 3;
                    int b4 = e & 7;
                    float4 v = __ldcg(&hsrc[(w << 9) + e]);
                    float* dst = Hs + ((w << 2) | (kl >> 4)) * 514
                                    + (kl & 15) * 32 + (b4 << 2);
                    *(float2*)dst       = make_float2(v.x, v.y);
                    *(float2*)(dst + 2) = make_float2(v.z, v.w);
                }
                __syncwarp();
            }

            // GEMV: 8 rows x 4 batch-pairs per lane over 16 k
            ull acc[8][4];
#pragma unroll
            for (int i = 0; i < 8; i++)
#pragma unroll
                for (int j = 0; j < 4; j++) acc[i][j] = 0ull;

#pragma unroll 8
            for (int kk = 0; kk < 16; kk++) {
                float4 w0 = Wr[(kk << 2) + (rg << 1)];       // rows 8rg..+3
                float4 w1 = Wr[(kk << 2) + (rg << 1) + 1];   // rows 8rg+4..+7
                const float* hb = Hr + (kk << 5) + (bg << 3);
                ull h0 = *(const ull*)(hb + 0);
                ull h1 = *(const ull*)(hb + 2);
                ull h2 = *(const ull*)(hb + 4);
                ull h3 = *(const ull*)(hb + 6);
#define ROWFMA(I, WF) { ull wd = dup2(WF); \
                ffma2(acc[I][0], wd, h0); ffma2(acc[I][1], wd, h1); \
                ffma2(acc[I][2], wd, h2); ffma2(acc[I][3], wd, h3); }
                ROWFMA(0, w0.x) ROWFMA(1, w0.y) ROWFMA(2, w0.z) ROWFMA(3, w0.w)
                ROWFMA(4, w1.x) ROWFMA(5, w1.y) ROWFMA(6, w1.z) ROWFMA(7, w1.w)
#undef ROWFMA
            }

            // 2-round k-fold (static register indices; R9-verified mapping)
            {
                float* gbX = d ? gbb : gbf;
                bool kA = (lane & 8) != 0;
                bool kB = (lane & 16) != 0;
                int p   = ((lane >> 2) & 2) | ((lane >> 4) & 1);
                float* gp0 = gbX + w * 544 + (bg << 3) + (p << 1);
#pragma unroll
                for (int i = 0; i < 8; i++) {
                    ull s0 = kA ? acc[i][0] : acc[i][2];
                    ull s1 = kA ? acc[i][1] : acc[i][3];
                    ull r0 = __shfl_xor_sync(0xFFFFFFFFu, s0, 8);
                    ull r1 = __shfl_xor_sync(0xFFFFFFFFu, s1, 8);
                    ull k0 = addf2(kA ? acc[i][2] : acc[i][0], r0);
                    ull k1 = addf2(kA ? acc[i][3] : acc[i][1], r1);
                    ull sb = kB ? k0 : k1;
                    ull rb = __shfl_xor_sync(0xFFFFFFFFu, sb, 16);
                    ull fin = addf2(kB ? k1 : k0, rb);
                    *(ull*)(gp0 + ((rg << 3) + i) * 34) = fin;
                }
            }
            __syncthreads();   // partials of this phase published

            // cell update for this direction's warp group; other group races
            // ahead into the next phase (overlap)
            if (half == d) {
                const float* gbX = d ? gbb : gbf;
                float iv = xg0, fv = xg1, gv = xg2, ov = xg3;
#pragma unroll
                for (int sw = 0; sw < 8; sw++) {
                    const float* gp = gbX + sw * 544 + lane;
                    iv += gp[(0 * 4 + wc) * 34];
                    fv += gp[(1 * 4 + wc) * 34];
                    gv += gp[(2 * 4 + wc) * 34];
                    ov += gp[(3 * 4 + wc) * 34];
                }
                iv = sigf(iv);
                fv = sigf(fv);
                gv = tanhfast(gv);
                ov = sigf(ov);
                float c_new = fv * c_reg + iv * gv;
                float h_new = ov * tanhfast(c_new);
                c_reg = 0.9f * c_new + 0.1f * c_reg;
                h_reg = 0.9f * h_new + 0.1f * h_reg;
                g_hbuf[d][(s + 1) & 1][gu * 32 + lane] = h_reg;
                // exactly two commutative fp32 adds per output element
                atomicAdd(&out[(size_t)t * (NB * HD) + lane * HD + gu], h_reg);
                if (d == 0) {
                    asm volatile("bar.sync 1, 128;" ::: "memory");
                    if (tid == 0) bar_arrive(0, genf, grp);
                } else {
                    asm volatile("bar.sync 2, 128;" ::: "memory");
                    if (tid == 128) bar_arrive(1, genb, grp);
                }
            }
        }
    }
}

// ---------------------------------------------------------------------------
extern "C" void kernel_launch(void* const* d_in, const int* in_sizes, int n_in,
                              void* d_out, int out_size) {
    const float* x   = (const float*)d_in[0];
    const float* Wih = (const float*)d_in[1];
    const float* Whh = (const float*)d_in[2];
    const float* bih = (const float*)d_in[3];
    const float* bhh = (const float*)d_in[4];
    float* out = (float*)d_out;

    const int rec_smem = (8320 + 16448 + 4352 + 4352) * (int)sizeof(float); // 133888 B
    cudaFuncSetAttribute(lstm_rec, cudaFuncAttributeMaxDynamicSharedMemorySize, rec_smem);

    xw_gemm<<<TSEQ * 32, 256>>>(x, Wih, bih, bhh, (float4*)out);
    lstm_rec<<<NBLK, REC_THREADS, rec_smem>>>(Whh, out);
}

// round 11
// speedup vs baseline: 1.2429x; 1.2429x over previous
#include <cuda_runtime.h>

// Problem constants
#define TSEQ 1024
#define NB   32      // batch
#define ID   512     // input dim
#define HD   512     // hidden dim
#define GD   2048    // 4*H gate rows
#define NBLK_DIR 64  // persistent blocks per direction (8 hidden units each)
#define REC_THREADS 256

typedef unsigned long long ull;

// Scratch (device globals: no runtime allocation allowed)
__device__ float g_xw[(size_t)TSEQ * GD * NB];   // [t][g][b], 256MB
__device__ float g_hbuf[2][2][HD * NB];          // [dir][ping][u*32 + b]
__device__ unsigned g_cnt[2][8];   // tree barrier: 8 groups of 8 (monotonic)
__device__ unsigned g_root[2];     // root counters (monotonic)
__device__ unsigned g_gen[2];      // generation flags (monotonic)

// ---------------------------------------------------------------------------
// packed fp32x2 ops (Blackwell)
// ---------------------------------------------------------------------------
__device__ __forceinline__ void ffma2(ull& d, ull a, ull b) {
    asm("fma.rn.f32x2 %0, %1, %2, %0;" : "+l"(d) : "l"(a), "l"(b));
}
__device__ __forceinline__ ull addf2(ull a, ull b) {
    ull r;
    asm("add.rn.f32x2 %0, %1, %2;" : "=l"(r) : "l"(a), "l"(b));
    return r;
}
__device__ __forceinline__ ull dup2(float x) {
    ull r;
    asm("mov.b64 %0, {%1, %1};" : "=l"(r) : "f"(x));
    return r;
}
__device__ __forceinline__ float pairsum(ull v) {
    float2 f = *reinterpret_cast<float2*>(&v);
    return f.x + f.y;
}

__device__ __forceinline__ unsigned atom_add_acqrel(unsigned* p, unsigned v) {
    unsigned old;
    asm volatile("atom.acq_rel.gpu.add.u32 %0, [%1], %2;"
                 : "=r"(old) : "l"(p), "r"(v) : "memory");
    return old;
}
__device__ __forceinline__ unsigned ld_acquire(const unsigned* p) {
    unsigned v;
    asm volatile("ld.acquire.gpu.u32 %0, [%1];" : "=r"(v) : "l"(p) : "memory");
    return v;
}
__device__ __forceinline__ void st_release(unsigned* p, unsigned v) {
    asm volatile("st.release.gpu.u32 [%0], %1;" :: "l"(p), "r"(v) : "memory");
}

__device__ __forceinline__ float sigf(float x) {
    return __fdividef(1.f, 1.f + __expf(-x));
}
__device__ __forceinline__ float tanhfast(float x) {
    return __fdividef(2.f, 1.f + __expf(-2.f * x)) - 1.f;
}

// Tree barrier (per direction): 64 blocks = 8 groups x 8. Arrive completing
// generation G releases G+1 via g_gen. All counters monotonic (replay-safe).
__device__ __forceinline__ void bar_arrive(int d, unsigned G, int grp) {
    unsigned old = atom_add_acqrel(&g_cnt[d][grp], 1u);
    if (old == G * 8u + 7u) {
        unsigned r = atom_add_acqrel(&g_root[d], 1u);
        if (r == G * 8u + 7u) st_release(&g_gen[d], G + 1u);
    }
}
__device__ __forceinline__ void bar_wait(int d, unsigned G) {
    while ((int)(ld_acquire(&g_gen[d]) - (G + 1u)) < 0) { }
}

// ---------------------------------------------------------------------------
// xw[t][g][b] = sum_i x[t][b][i] * W_ih[g][i] + (b_ih[g] + b_hh[g])
// Also zeroes its 2KB slice of d_out.  (unchanged from R8)
// ---------------------------------------------------------------------------
__global__ __launch_bounds__(256) void xw_gemm(
    const float* __restrict__ x,
    const float* __restrict__ Wih,
    const float* __restrict__ bih,
    const float* __restrict__ bhh,
    float4* __restrict__ out4)
{
    __shared__ float xs[NB * 36];
    __shared__ float ws[64 * 32];

    if (threadIdx.x < 128)
        out4[(size_t)blockIdx.x * 128 + threadIdx.x] = make_float4(0.f, 0.f, 0.f, 0.f);

    int t   = blockIdx.x >> 5;
    int g0  = (blockIdx.x & 31) << 6;
    int tid = threadIdx.x;
    int gg  = tid >> 5;
    int b   = tid & 31;

    ull acc[8];
#pragma unroll
    for (int j = 0; j < 8; j++) acc[j] = 0ull;

    const float* xt = x + (size_t)t * NB * ID;

    for (int k0 = 0; k0 < ID; k0 += 32) {
#pragma unroll
        for (int r = 0; r < 4; r++) {
            int bl = (tid >> 5) + (r << 3);
            int kk = tid & 31;
            xs[bl * 36 + kk] = xt[bl * ID + k0 + kk];
        }
#pragma unroll
        for (int r = 0; r < 8; r++) {
            int gl = (tid >> 5) + (r << 3);
            int kk = tid & 31;
            ws[gl * 32 + kk] = Wih[(size_t)(g0 + gl) * ID + k0 + kk];
        }
        __syncthreads();

#pragma unroll
        for (int kk = 0; kk < 32; kk += 4) {
            ulonglong2 xv = *(const ulonglong2*)&xs[b * 36 + kk];
#pragma unroll
            for (int j = 0; j < 8; j++) {
                ulonglong2 wv = *(const ulonglong2*)&ws[(gg * 8 + j) * 32 + kk];
                ffma2(acc[j], xv.x, wv.x);
                ffma2(acc[j], xv.y, wv.y);
            }
        }
        __syncthreads();
    }

    float* outp = g_xw + (size_t)t * GD * NB;
#pragma unroll
    for (int j = 0; j < 8; j++) {
        int g = g0 + gg * 8 + j;
        outp[g * NB + b] = pairsum(acc[j]) + bih[g] + bhh[g];
    }
}

// ---------------------------------------------------------------------------
// Persistent bidirectional zoneout-LSTM recurrence (R8 compute structure).
// 128 blocks: 0..63 fwd, 64..127 bwd. Block: 8 hidden units (32 gate rows) x 32 b.
// GEMV: lane = (ks0 = lane>>4, rg = (lane>>2)&1... see R8) — 8 rows x 4
// batch-pairs per lane over 32 k; static-index shfl fold.
// R11 deltas: tree barrier, atomicAdd(out) after arrive, c/h_old in registers.
// ---------------------------------------------------------------------------
__global__ __launch_bounds__(REC_THREADS, 1) void lstm_rec(
    const float* __restrict__ Whh, float* __restrict__ out)
{
    extern __shared__ float smem[];
    float* Wt   = smem;             // 64KB: Wt[k*32 + row]
    float* Hs   = smem + 16384;     // 64KB: Hs[u*32 + b]
    float* gbuf = smem + 32768;     // 34KB: gbuf[w*1088 + row*34 + b]

    int bid  = blockIdx.x;
    int dir  = bid >> 6;
    int grp  = (bid & 63) >> 3;
    int tid  = threadIdx.x;
    int w    = tid >> 5;
    int lane = tid & 31;
    int ks0  = lane >> 4;
    int rg   = (lane >> 2) & 3;
    int bg   = lane & 3;
    int j0   = (bid & 63) << 3;
    int u_l  = w;               // cell phase: unit-local 0..7
    int gu   = j0 + u_l;

    // Stage W_hh once: Wt[k*32 + row], row -> global W row (row>>3)*512 + j0 + (row&7)
#pragma unroll 4
    for (int i = 0; i < 64; i++) {
        int idx = tid + (i << 8);
        int row = idx >> 9;
        int k   = idx & 511;
        int gr  = ((row >> 3) << 9) + j0 + (row & 7);
        Wt[k * 32 + row] = Whh[(size_t)gr * HD + k];
    }

    // init h(step 0) = 0 (own units); c and h_old live in registers
    float c_reg = 0.f;
    float h_reg = 0.f;
    g_hbuf[dir][0][gu * 32 + lane] = 0.f;

    unsigned gen = ld_acquire(&g_gen[dir]);   // monotonic base (replay-safe)
    __syncthreads();
    if (tid == 0) bar_arrive(dir, gen, grp);  // publish h0

    const float4* W4 = (const float4*)Wt;
    const float4* H4 = (const float4*)Hs;
    const int kbeg = (w << 6) + (ks0 << 5);

    for (int s = 0; s < TSEQ; s++) {
        // wait for generation gen+... : all blocks' h of step s published
        if (tid == 0) bar_wait(dir, gen);
        __syncthreads();
        gen++;

        int t = dir ? (TSEQ - 1 - s) : s;
        const float* xw_t = g_xw + (size_t)t * GD * NB;

        // prefetch xw for the cell phase (hidden under GEMV)
        float xg0 = xw_t[(0 * HD + gu) * NB + lane];
        float xg1 = xw_t[(1 * HD + gu) * NB + lane];
        float xg2 = xw_t[(2 * HD + gu) * NB + lane];
        float xg3 = xw_t[(3 * HD + gu) * NB + lane];

        // per-warp copy of its own h k-range [64w, 64w+64): float4 [512w, 512w+512)
        {
            const float4* hsrc = (const float4*)g_hbuf[dir][s & 1];
            float4* hdst = (float4*)Hs;
#pragma unroll
            for (int i = 0; i < 16; i++) {
                int idx = (w << 9) + (i << 5) + lane;
                hdst[idx] = __ldcg(&hsrc[idx]);
            }
            __syncwarp();   // order cross-lane STS -> LDS within this warp
        }

        // GEMV: 8 rows x 4 batch-pairs per lane over 32 k
        ull acc[8][4];
#pragma unroll
        for (int i = 0; i < 8; i++)
#pragma unroll
            for (int j = 0; j < 4; j++) acc[i][j] = 0ull;

#pragma unroll 4
        for (int kk = 0; kk < 32; kk++) {
            int k = kbeg + kk;
            float4 wA = W4[(k << 3) + (rg << 1)];       // rows 8rg..8rg+3
            float4 wB = W4[(k << 3) + (rg << 1) + 1];   // rows 8rg+4..8rg+7
            ulonglong2 hA = *(const ulonglong2*)&H4[(k << 3) + (bg << 1)];
            ulonglong2 hB = *(const ulonglong2*)&H4[(k << 3) + (bg << 1) + 1];
            float wf[8] = {wA.x, wA.y, wA.z, wA.w, wB.x, wB.y, wB.z, wB.w};
#pragma unroll
            for (int i = 0; i < 8; i++) {
                ull wd = dup2(wf[i]);
                ffma2(acc[i][0], wd, hA.x);
                ffma2(acc[i][1], wd, hA.y);
                ffma2(acc[i][2], wd, hB.x);
                ffma2(acc[i][3], wd, hB.y);
            }
        }

        // fold k-halves + store: STATIC indices only (R7 lesson)
        {
            float* gp0 = gbuf + w * 1088 + (bg << 3) + (ks0 << 2);
#pragma unroll
            for (int i = 0; i < 8; i++) {
                ull s0 = ks0 ? acc[i][0] : acc[i][2];
                ull s1 = ks0 ? acc[i][1] : acc[i][3];
                ull r0 = __shfl_xor_sync(0xFFFFFFFFu, s0, 16);
                ull r1 = __shfl_xor_sync(0xFFFFFFFFu, s1, 16);
                ull k0 = ks0 ? acc[i][2] : acc[i][0];
                ull k1 = ks0 ? acc[i][3] : acc[i][1];
                ull v0 = addf2(k0, r0);
                ull v1 = addf2(k1, r1);
                float* gp = gp0 + ((rg << 3) + i) * 34;
                *(ull*)gp = v0;
                *(ull*)(gp + 2) = v1;
            }
        }
        __syncthreads();

        // cell update: thread = (unit u_l = w, batch lane); 8 partial sets per gate
        float h_bl;
        {
            int b = lane;
            float iv = xg0, fv = xg1, gv = xg2, ov = xg3;
#pragma unroll
            for (int sw = 0; sw < 8; sw++) {
                const float* gp = gbuf + sw * 1088 + b;
                iv += gp[(0 * 8 + u_l) * 34];
                fv += gp[(1 * 8 + u_l) * 34];
                gv += gp[(2 * 8 + u_l) * 34];
                ov += gp[(3 * 8 + u_l) * 34];
            }
            iv = sigf(iv);
            fv = sigf(fv);
            gv = tanhfast(gv);
            ov = sigf(ov);
            float c_new = fv * c_reg + iv * gv;
            float h_new = ov * tanhfast(c_new);
            c_reg = 0.9f * c_new + 0.1f * c_reg;
            h_bl  = 0.9f * h_new + 0.1f * h_reg;
            h_reg = h_bl;
            g_hbuf[dir][(s + 1) & 1][gu * 32 + lane] = h_bl;
        }

        // publish h_{s+1}: sync, arrive (critical path), THEN the out atomic
        __syncthreads();
        if (tid == 0) bar_arrive(dir, gen, grp);
        // exactly two commutative fp32 adds per output element -> deterministic;
        // off the inter-block critical path (overlaps the next wait)
        atomicAdd(&out[(size_t)t * (NB * HD) + lane * HD + gu], h_bl);
    }
}

// ---------------------------------------------------------------------------
extern "C" void kernel_launch(void* const* d_in, const int* in_sizes, int n_in,
                              void* d_out, int out_size) {
    const float* x   = (const float*)d_in[0];
    const float* Wih = (const float*)d_in[1];
    const float* Whh = (const float*)d_in[2];
    const float* bih = (const float*)d_in[3];
    const float* bhh = (const float*)d_in[4];
    float* out = (float*)d_out;

    const int rec_smem = (16384 + 16384 + 8 * 1088) * (int)sizeof(float); // 165888 B
    cudaFuncSetAttribute(lstm_rec, cudaFuncAttributeMaxDynamicSharedMemorySize, rec_smem);

    xw_gemm<<<TSEQ * 32, 256>>>(x, Wih, bih, bhh, (float4*)out);
    lstm_rec<<<2 * NBLK_DIR, REC_THREADS, rec_smem>>>(Whh, out);
}